// round 2
// baseline (speedup 1.0000x reference)
#include <cuda_runtime.h>
#include <math.h>

#define B_TOTAL 65536
#define OBS 64
#define ACTD 16
#define IND 145
#define HID 256
#define FEAT 128
#define NENV 64
#define EMB 32
#define ROWS 64
#define NTHREADS 256

// ---- shared memory layout (float offsets) ----
#define SX_STRIDE 152
#define OFF_SX    0                       // 64*152 = 9728   (x input; later aliased by FEAT)
#define OFF_SA    9728                    // 64*256 = 16384  (h0; later W tile)
#define OFF_SB    (9728+16384)            // 64*256 = 16384  (h1; later f2e/best)
#define OFF_FEAT  0                       // 64*128 = 8192 (aliases SX, stride 128)
#define OFF_W     9728                    // 128*132 = 16896 (transposed W_proj tile)
#define WS_STRIDE 132
#define OFF_F2E   (9728+16896)            // 64*132 = 8448
#define F2E_STRIDE 132
#define OFF_BEST  (9728+16896+8448)       // 64*32 = 2048
#define OFF_DLOC  (OFF_BEST+2048)         // 64*4 = 256
#define OFF_EEMB  42496                   // 64*32 = 2048
#define OFF_COEF  (OFF_EEMB+2048)         // 64
#define OFF_MIND  (OFF_COEF+64)           // 64
#define OFF_MIDX  (OFF_MIND+64)           // 64 (ints)
#define OFF_WNL   (OFF_MIDX+64)           // 64 (ints)
#define SMEM_FLOATS (OFF_WNL+64)          // 44800 floats = 179200 bytes

// Dense layer: out[r][c] = leaky(sum_k in[r][k] * W[k*C+c] + b[c])
// thread layout: tx = tid%64 -> cols {tx + 64*j}, ty = tid/64 -> rows [ty*16, ty*16+16)
template<int NJ>
__device__ __forceinline__ void dense_layer(
    const float* __restrict__ in_s, int in_stride, int K,
    const float* __restrict__ W, const float* __restrict__ bias,
    float* __restrict__ out_s, int out_stride, int C, int tid)
{
    const int tx = tid & 63;
    const int ty = tid >> 6;
    float acc[16][NJ];
#pragma unroll
    for (int j = 0; j < NJ; j++) {
        float bb = __ldg(&bias[tx + 64 * j]);
#pragma unroll
        for (int rr = 0; rr < 16; rr++) acc[rr][j] = bb;
    }
    const float* ip = in_s + (ty * 16) * in_stride;
#pragma unroll 2
    for (int k = 0; k < K; k++) {
        float w[NJ];
#pragma unroll
        for (int j = 0; j < NJ; j++) w[j] = __ldg(&W[(size_t)k * C + tx + 64 * j]);
#pragma unroll
        for (int rr = 0; rr < 16; rr++) {
            float xv = ip[rr * in_stride + k];
#pragma unroll
            for (int j = 0; j < NJ; j++) acc[rr][j] = fmaf(xv, w[j], acc[rr][j]);
        }
    }
#pragma unroll
    for (int rr = 0; rr < 16; rr++) {
#pragma unroll
        for (int j = 0; j < NJ; j++) {
            float a = acc[rr][j];
            out_s[(ty * 16 + rr) * out_stride + tx + 64 * j] = fmaxf(a, 0.01f * a);
        }
    }
}

extern __shared__ float sm[];

__global__ void __launch_bounds__(NTHREADS, 1)
udp_encoder_kernel(
    const float* __restrict__ obs,  const float* __restrict__ act,
    const float* __restrict__ obs2, const float* __restrict__ rew,
    const float* __restrict__ W0,   const float* __restrict__ b0,
    const float* __restrict__ W1,   const float* __restrict__ b1,
    const float* __restrict__ W2,   const float* __restrict__ b2,
    const float* __restrict__ Wp,   const float* __restrict__ ee,
    const float* __restrict__ sig,  float* __restrict__ out)
{
    const int tid = threadIdx.x;
    const int blk = blockIdx.x;
    const size_t row0 = (size_t)blk * ROWS;

    // ---- load e_emb, sigma coefficients, init argmin state ----
    for (int i = tid; i < NENV * EMB; i += NTHREADS) sm[OFF_EEMB + i] = ee[i];
    if (tid < NENV) {
        float s = sig[tid];
        sm[OFF_COEF + tid] = -1.0f / (64.0f * s * s);   // exp(-sumsq/(64*s^2))
        sm[OFF_MIND + tid] = 3.0e38f;
        ((int*)sm)[OFF_MIDX + tid] = 0;
    }

    // ---- build input tile x = [obs, obs2-obs, act, rew]  (64 x 145) ----
    for (int i = tid; i < ROWS * OBS; i += NTHREADS) {
        int r = i >> 6, k = i & 63;
        float o  = obs [(row0 + r) * OBS + k];
        float o2 = obs2[(row0 + r) * OBS + k];
        sm[OFF_SX + r * SX_STRIDE + k]      = o;
        sm[OFF_SX + r * SX_STRIDE + 64 + k] = o2 - o;
    }
    for (int i = tid; i < ROWS * ACTD; i += NTHREADS) {
        int r = i >> 4, k = i & 15;
        sm[OFF_SX + r * SX_STRIDE + 128 + k] = act[(row0 + r) * ACTD + k];
    }
    if (tid < ROWS) sm[OFF_SX + tid * SX_STRIDE + 144] = rew[row0 + tid];
    __syncthreads();

    // ---- MLP ----
    dense_layer<4>(sm + OFF_SX, SX_STRIDE, IND, W0, b0, sm + OFF_SA, HID, HID, tid);
    __syncthreads();
    dense_layer<4>(sm + OFF_SA, HID, HID, W1, b1, sm + OFF_SB, HID, HID, tid);
    __syncthreads();
    dense_layer<2>(sm + OFF_SB, HID, HID, W2, b2, sm + OFF_FEAT, FEAT, FEAT, tid);
    __syncthreads();

    // ---- projection + distance + argmin, 4 envs per group ----
    const int cg = tid & 31;   // col group: 4 cols (one env, 4 emb dims)
    const int rg = tid >> 5;   // 8 row groups of 8 rows

    for (int g = 0; g < 16; g++) {
        // stage W_proj tile transposed: w_s[k][c], c = nl*32+e, stride 132
        for (int i = tid; i < 128 * 128; i += NTHREADS) {
            int c = i >> 7, k = i & 127;
            sm[OFF_W + k * WS_STRIDE + c] =
                Wp[((size_t)(g * 4 + (c >> 5)) * EMB + (c & 31)) * FEAT + k];
        }
        __syncthreads();

        float acc[8][4];
#pragma unroll
        for (int rr = 0; rr < 8; rr++)
#pragma unroll
            for (int j = 0; j < 4; j++) acc[rr][j] = 0.0f;

        const float* fp = sm + OFF_FEAT + (rg * 8) * FEAT;
#pragma unroll 2
        for (int k = 0; k < FEAT; k++) {
            float4 w = *(const float4*)(sm + OFF_W + k * WS_STRIDE + cg * 4);
#pragma unroll
            for (int rr = 0; rr < 8; rr++) {
                float xv = fp[rr * FEAT + k];
                acc[rr][0] = fmaf(xv, w.x, acc[rr][0]);
                acc[rr][1] = fmaf(xv, w.y, acc[rr][1]);
                acc[rr][2] = fmaf(xv, w.z, acc[rr][2]);
                acc[rr][3] = fmaf(xv, w.w, acc[rr][3]);
            }
        }
#pragma unroll
        for (int rr = 0; rr < 8; rr++) {
            int r = rg * 8 + rr;
            *(float4*)(sm + OFF_F2E + r * F2E_STRIDE + cg * 4) =
                make_float4(acc[rr][0], acc[rr][1], acc[rr][2], acc[rr][3]);
        }
        __syncthreads();

        // distances: thread -> (r = tid/4, nl = tid%4)
        {
            int r = tid >> 2, nl = tid & 3;
            const float* fv = sm + OFF_F2E + r * F2E_STRIDE + nl * 32;
            const float* ev = sm + OFF_EEMB + (g * 4 + nl) * 32;
            float ssum = 0.0f;
#pragma unroll
            for (int e = 0; e < 32; e++) { float d = fv[e] - ev[e]; ssum = fmaf(d, d, ssum); }
            int n = g * 4 + nl;
            float dist = expf(ssum * sm[OFF_COEF + n]);
            out[(size_t)B_TOTAL * 66 + (row0 + r) * 64 + n] = dist;  // distance output
            sm[OFF_DLOC + r * 4 + nl] = dist;
        }
        __syncthreads();

        // argmin update (strict <, ascending n = first-min semantics)
        if (tid < ROWS) {
            int r = tid;
            float mind = sm[OFF_MIND + r];
            int wn = -1;
#pragma unroll
            for (int nl = 0; nl < 4; nl++) {
                float d = sm[OFF_DLOC + r * 4 + nl];
                if (d < mind) { mind = d; wn = nl; }
            }
            sm[OFF_MIND + r] = mind;
            if (wn >= 0) ((int*)sm)[OFF_MIDX + r] = g * 4 + wn;
            ((int*)sm)[OFF_WNL + r] = wn;
        }
        __syncthreads();

        // copy winning embedding into best buffer
        {
            int r = tid >> 2, part = tid & 3;
            int wn = ((int*)sm)[OFF_WNL + r];
            if (wn >= 0) {
#pragma unroll
                for (int e = 0; e < 8; e++)
                    sm[OFF_BEST + r * 32 + part * 8 + e] =
                        sm[OFF_F2E + r * F2E_STRIDE + wn * 32 + part * 8 + e];
            }
        }
        __syncthreads();
    }

    // ---- final outputs ----
    const int* midx = (const int*)sm + OFF_MIDX;
    for (int i = tid; i < ROWS * EMB; i += NTHREADS) {
        int r = i >> 5, e = i & 31;
        size_t grow = row0 + r;
        out[grow * 32 + e] = sm[OFF_BEST + r * 32 + e];                           // chosen_embedding
        out[(size_t)B_TOTAL * 34 + grow * 32 + e] = sm[OFF_EEMB + midx[r] * 32 + e]; // chosen_mean
    }
    if (tid < ROWS) {
        size_t grow = row0 + tid;
        out[(size_t)B_TOTAL * 32 + grow] = sm[OFF_MIND + tid];   // chosen_dist
        out[(size_t)B_TOTAL * 33 + grow] = (float)midx[tid];     // idx
    }
}

extern "C" void kernel_launch(void* const* d_in, const int* in_sizes, int n_in,
                              void* d_out, int out_size) {
    const float* obs  = (const float*)d_in[0];
    const float* act  = (const float*)d_in[1];
    const float* obs2 = (const float*)d_in[2];
    const float* rew  = (const float*)d_in[3];
    const float* W0   = (const float*)d_in[4];
    const float* b0   = (const float*)d_in[5];
    const float* W1   = (const float*)d_in[6];
    const float* b1   = (const float*)d_in[7];
    const float* W2   = (const float*)d_in[8];
    const float* b2   = (const float*)d_in[9];
    const float* Wp   = (const float*)d_in[10];
    const float* ee   = (const float*)d_in[11];
    const float* sig  = (const float*)d_in[12];
    float* out = (float*)d_out;

    const size_t smem_bytes = (size_t)SMEM_FLOATS * sizeof(float); // 179200
    cudaFuncSetAttribute(udp_encoder_kernel,
                         cudaFuncAttributeMaxDynamicSharedMemorySize, (int)smem_bytes);

    dim3 grid(B_TOTAL / ROWS);   // 1024 blocks
    dim3 block(NTHREADS);
    udp_encoder_kernel<<<grid, block, smem_bytes>>>(
        obs, act, obs2, rew, W0, b0, W1, b1, W2, b2, Wp, ee, sig, out);
}